// round 1
// baseline (speedup 1.0000x reference)
#include <cuda_runtime.h>
#include <cuda_bf16.h>
#include <math.h>

// Problem constants
#define BATCH   8
#define SEQ     1024
#define DMODEL  2048
#define NHEAD   16
#define HEADDIM 128
#define MROWS   (BATCH * SEQ)          // 8192
#define HALF_D  (DMODEL / 2)           // 1024
#define SCALE   0.02209708691207961f   // 1/sqrt(2048)

// -------------------- device scratch (no runtime allocation allowed) ------
__device__ float g_q  [MROWS * DMODEL];
__device__ float g_k  [MROWS * DMODEL];
__device__ float g_v  [MROWS * DMODEL];
__device__ float g_ctx[MROWS * DMODEL];
__device__ float g_cos[SEQ * HALF_D];
__device__ float g_sin[SEQ * HALF_D];

// -------------------- RoPE table ------------------------------------------
// inv_freq[p] = theta^(-2p/d) = exp(-p * ln(1e4)/1024); angle = t * inv_freq
__global__ void rope_table_kernel() {
    int idx = blockIdx.x * blockDim.x + threadIdx.x;   // SEQ*HALF_D = 1<<20 threads
    int t = idx >> 10;
    int p = idx & 1023;
    float inv  = expf(-(float)p * (9.210340371976184f / 1024.0f));
    float ang  = (float)t * inv;
    float s, c;
    sincosf(ang, &s, &c);
    g_cos[idx] = c;
    g_sin[idx] = s;
}

// -------------------- projection GEMM: C[m,n] = sum_k A[m,k] * W[n,k] -----
// A: [8192,2048] row-major, W: [2048,2048] row-major, C: [8192,2048].
// 128x128 tile, BK=16, 256 threads, 8x8 micro-tile per thread.
// rope != 0: apply rotary rotation to output pairs in the epilogue.
#define BM 128
#define BN 128
#define BK 16

__global__ __launch_bounds__(256)
void gemm128_kernel(const float* __restrict__ A,
                    const float* __restrict__ W,
                    float* __restrict__ C,
                    int rope)
{
    __shared__ float As[BK][BM];   // stored transposed: As[k][m]
    __shared__ float Bs[BK][BN];   // Bs[k][n]

    const int tid = threadIdx.x;
    const int tx  = tid & 15;          // col group 0..15
    const int ty  = tid >> 4;          // row group 0..15
    const int m0  = blockIdx.x * BM;
    const int n0  = blockIdx.y * BN;

    float acc[8][8];
#pragma unroll
    for (int i = 0; i < 8; i++)
#pragma unroll
        for (int j = 0; j < 8; j++) acc[i][j] = 0.f;

    for (int k0 = 0; k0 < DMODEL; k0 += BK) {
        // load A tile (128 rows x 16 cols) as float4, store transposed
#pragma unroll
        for (int it = 0; it < 2; it++) {
            int f   = tid + it * 256;          // 0..511
            int row = f >> 2;
            int kv  = f & 3;
            float4 v = *(const float4*)&A[(size_t)(m0 + row) * DMODEL + k0 + kv * 4];
            As[kv * 4 + 0][row] = v.x;
            As[kv * 4 + 1][row] = v.y;
            As[kv * 4 + 2][row] = v.z;
            As[kv * 4 + 3][row] = v.w;
        }
        // load W tile (128 N-rows x 16 k-cols), store transposed
#pragma unroll
        for (int it = 0; it < 2; it++) {
            int f   = tid + it * 256;
            int row = f >> 2;
            int kv  = f & 3;
            float4 v = *(const float4*)&W[(size_t)(n0 + row) * DMODEL + k0 + kv * 4];
            Bs[kv * 4 + 0][row] = v.x;
            Bs[kv * 4 + 1][row] = v.y;
            Bs[kv * 4 + 2][row] = v.z;
            Bs[kv * 4 + 3][row] = v.w;
        }
        __syncthreads();

#pragma unroll
        for (int k = 0; k < BK; k++) {
            float a[8], b[8];
            *(float4*)&a[0] = *(const float4*)&As[k][ty * 4];
            *(float4*)&a[4] = *(const float4*)&As[k][ty * 4 + 64];
            *(float4*)&b[0] = *(const float4*)&Bs[k][tx * 4];
            *(float4*)&b[4] = *(const float4*)&Bs[k][tx * 4 + 64];
#pragma unroll
            for (int i = 0; i < 8; i++)
#pragma unroll
                for (int j = 0; j < 8; j++)
                    acc[i][j] = fmaf(a[i], b[j], acc[i][j]);
        }
        __syncthreads();
    }

    // epilogue (+ optional RoPE on consecutive pairs)
#pragma unroll
    for (int i = 0; i < 8; i++) {
        int rloc = ty * 4 + (i & 3) + ((i >> 2) << 6);
        int gm   = m0 + rloc;
        int t    = gm & (SEQ - 1);
#pragma unroll
        for (int g = 0; g < 2; g++) {
            int   nG = n0 + tx * 4 + g * 64;
            float v0 = acc[i][g * 4 + 0];
            float v1 = acc[i][g * 4 + 1];
            float v2 = acc[i][g * 4 + 2];
            float v3 = acc[i][g * 4 + 3];
            float4 out;
            if (rope) {
                int   p  = nG >> 1;
                float c0 = g_cos[t * HALF_D + p];
                float s0 = g_sin[t * HALF_D + p];
                float c1 = g_cos[t * HALF_D + p + 1];
                float s1 = g_sin[t * HALF_D + p + 1];
                out.x = v0 * c0 - v1 * s0;
                out.y = v0 * s0 + v1 * c0;
                out.z = v2 * c1 - v3 * s1;
                out.w = v2 * s1 + v3 * c1;
            } else {
                out.x = v0; out.y = v1; out.z = v2; out.w = v3;
            }
            *(float4*)&C[(size_t)gm * DMODEL + nG] = out;
        }
    }
}

// -------------------- flash attention -------------------------------------
// One block per (q-tile=64, head, batch). 256 threads = 16x16 grid:
//   S tile: thread(tr,tc) computes S[tr*4+i][tc*4+j]     (64x64)
//   O tile: thread(tr,tc) computes O[tr*4+i][tc*8+j]     (64x128)
// smem: Qt[128][65] | (Kt[128][65] union Vs[64][128]) | Ps[64][65]
#define BQ  64
#define BKV 64
#define QT_STRIDE 65
#define SM_QT 0
#define SM_KV (HEADDIM * QT_STRIDE)            // 8320
#define SM_PS (SM_KV + HEADDIM * QT_STRIDE)    // 16640
#define SM_FLOATS (SM_PS + BQ * QT_STRIDE)     // 20800 floats = 83200 B

__global__ __launch_bounds__(256, 2)
void flash_kernel(const float* __restrict__ Q,
                  const float* __restrict__ K,
                  const float* __restrict__ V,
                  float* __restrict__ O)
{
    extern __shared__ float sm[];
    float* Qt = sm + SM_QT;   // [128][65] transposed, pre-scaled
    float* KV = sm + SM_KV;   // Kt[128][65] OR Vs[64][128]
    float* Ps = sm + SM_PS;   // [64][65]

    const int tid = threadIdx.x;
    const int tc  = tid & 15;
    const int tr  = tid >> 4;
    const int q0  = blockIdx.x * BQ;
    const int h   = blockIdx.y;
    const int b   = blockIdx.z;
    const size_t base = (size_t)b * SEQ * DMODEL + (size_t)h * HEADDIM;

    // load Q tile transposed + pre-scale
    for (int idx = tid; idx < BQ * (HEADDIM / 4); idx += 256) {
        int row = idx >> 5;          // 0..63
        int kv  = idx & 31;          // float4 index over headdim
        float4 v = *(const float4*)&Q[base + (size_t)(q0 + row) * DMODEL + kv * 4];
        Qt[(kv * 4 + 0) * QT_STRIDE + row] = v.x * SCALE;
        Qt[(kv * 4 + 1) * QT_STRIDE + row] = v.y * SCALE;
        Qt[(kv * 4 + 2) * QT_STRIDE + row] = v.z * SCALE;
        Qt[(kv * 4 + 3) * QT_STRIDE + row] = v.w * SCALE;
    }

    float m_i[4], l_i[4], o[4][8];
#pragma unroll
    for (int i = 0; i < 4; i++) {
        m_i[i] = -1e30f;
        l_i[i] = 0.f;
#pragma unroll
        for (int j = 0; j < 8; j++) o[i][j] = 0.f;
    }
    __syncthreads();

    for (int kt = 0; kt < SEQ / BKV; kt++) {
        const int k0 = kt * BKV;

        // load K tile transposed (prior PV finished via loop-end sync)
        for (int idx = tid; idx < BKV * (HEADDIM / 4); idx += 256) {
            int row = idx >> 5;
            int kv  = idx & 31;
            float4 v = *(const float4*)&K[base + (size_t)(k0 + row) * DMODEL + kv * 4];
            KV[(kv * 4 + 0) * QT_STRIDE + row] = v.x;
            KV[(kv * 4 + 1) * QT_STRIDE + row] = v.y;
            KV[(kv * 4 + 2) * QT_STRIDE + row] = v.z;
            KV[(kv * 4 + 3) * QT_STRIDE + row] = v.w;
        }
        __syncthreads();

        // S = (Q*scale) @ K^T   (64x64 over hd=128)
        float s[4][4];
#pragma unroll
        for (int i = 0; i < 4; i++)
#pragma unroll
            for (int j = 0; j < 4; j++) s[i][j] = 0.f;

#pragma unroll 4
        for (int kk = 0; kk < HEADDIM; kk++) {
            float a0 = Qt[kk * QT_STRIDE + tr * 4 + 0];
            float a1 = Qt[kk * QT_STRIDE + tr * 4 + 1];
            float a2 = Qt[kk * QT_STRIDE + tr * 4 + 2];
            float a3 = Qt[kk * QT_STRIDE + tr * 4 + 3];
            float b0 = KV[kk * QT_STRIDE + tc * 4 + 0];
            float b1 = KV[kk * QT_STRIDE + tc * 4 + 1];
            float b2 = KV[kk * QT_STRIDE + tc * 4 + 2];
            float b3 = KV[kk * QT_STRIDE + tc * 4 + 3];
            s[0][0] = fmaf(a0, b0, s[0][0]); s[0][1] = fmaf(a0, b1, s[0][1]);
            s[0][2] = fmaf(a0, b2, s[0][2]); s[0][3] = fmaf(a0, b3, s[0][3]);
            s[1][0] = fmaf(a1, b0, s[1][0]); s[1][1] = fmaf(a1, b1, s[1][1]);
            s[1][2] = fmaf(a1, b2, s[1][2]); s[1][3] = fmaf(a1, b3, s[1][3]);
            s[2][0] = fmaf(a2, b0, s[2][0]); s[2][1] = fmaf(a2, b1, s[2][1]);
            s[2][2] = fmaf(a2, b2, s[2][2]); s[2][3] = fmaf(a2, b3, s[2][3]);
            s[3][0] = fmaf(a3, b0, s[3][0]); s[3][1] = fmaf(a3, b1, s[3][1]);
            s[3][2] = fmaf(a3, b2, s[3][2]); s[3][3] = fmaf(a3, b3, s[3][3]);
        }

        // online softmax update (row stats reduced over the 16 tc lanes)
#pragma unroll
        for (int i = 0; i < 4; i++) {
            float mx = fmaxf(fmaxf(s[i][0], s[i][1]), fmaxf(s[i][2], s[i][3]));
#pragma unroll
            for (int off = 1; off < 16; off <<= 1)
                mx = fmaxf(mx, __shfl_xor_sync(0xffffffffu, mx, off));
            float mnew  = fmaxf(m_i[i], mx);
            float alpha = __expf(m_i[i] - mnew);
            m_i[i] = mnew;
            float rs = 0.f;
#pragma unroll
            for (int j = 0; j < 4; j++) {
                s[i][j] = __expf(s[i][j] - mnew);
                rs += s[i][j];
            }
#pragma unroll
            for (int off = 1; off < 16; off <<= 1)
                rs += __shfl_xor_sync(0xffffffffu, rs, off);
            l_i[i] = l_i[i] * alpha + rs;
#pragma unroll
            for (int j = 0; j < 8; j++) o[i][j] *= alpha;
        }
        __syncthreads();   // all S-compute reads of Kt done

        // write P, load V into the same smem region as K
#pragma unroll
        for (int i = 0; i < 4; i++)
#pragma unroll
            for (int j = 0; j < 4; j++)
                Ps[(tr * 4 + i) * QT_STRIDE + tc * 4 + j] = s[i][j];

        for (int idx = tid; idx < BKV * (HEADDIM / 4); idx += 256) {
            int row = idx >> 5;
            int kv  = idx & 31;
            float4 v = *(const float4*)&V[base + (size_t)(k0 + row) * DMODEL + kv * 4];
            *(float4*)&KV[row * HEADDIM + kv * 4] = v;
        }
        __syncthreads();

        // O += P @ V   (64x128 over 64)
#pragma unroll 2
        for (int kk = 0; kk < BKV; kk++) {
            float p0 = Ps[(tr * 4 + 0) * QT_STRIDE + kk];
            float p1 = Ps[(tr * 4 + 1) * QT_STRIDE + kk];
            float p2 = Ps[(tr * 4 + 2) * QT_STRIDE + kk];
            float p3 = Ps[(tr * 4 + 3) * QT_STRIDE + kk];
            float4 va = *(const float4*)&KV[kk * HEADDIM + tc * 8];
            float4 vb = *(const float4*)&KV[kk * HEADDIM + tc * 8 + 4];
            o[0][0] = fmaf(p0, va.x, o[0][0]); o[0][1] = fmaf(p0, va.y, o[0][1]);
            o[0][2] = fmaf(p0, va.z, o[0][2]); o[0][3] = fmaf(p0, va.w, o[0][3]);
            o[0][4] = fmaf(p0, vb.x, o[0][4]); o[0][5] = fmaf(p0, vb.y, o[0][5]);
            o[0][6] = fmaf(p0, vb.z, o[0][6]); o[0][7] = fmaf(p0, vb.w, o[0][7]);
            o[1][0] = fmaf(p1, va.x, o[1][0]); o[1][1] = fmaf(p1, va.y, o[1][1]);
            o[1][2] = fmaf(p1, va.z, o[1][2]); o[1][3] = fmaf(p1, va.w, o[1][3]);
            o[1][4] = fmaf(p1, vb.x, o[1][4]); o[1][5] = fmaf(p1, vb.y, o[1][5]);
            o[1][6] = fmaf(p1, vb.z, o[1][6]); o[1][7] = fmaf(p1, vb.w, o[1][7]);
            o[2][0] = fmaf(p2, va.x, o[2][0]); o[2][1] = fmaf(p2, va.y, o[2][1]);
            o[2][2] = fmaf(p2, va.z, o[2][2]); o[2][3] = fmaf(p2, va.w, o[2][3]);
            o[2][4] = fmaf(p2, vb.x, o[2][4]); o[2][5] = fmaf(p2, vb.y, o[2][5]);
            o[2][6] = fmaf(p2, vb.z, o[2][6]); o[2][7] = fmaf(p2, vb.w, o[2][7]);
            o[3][0] = fmaf(p3, va.x, o[3][0]); o[3][1] = fmaf(p3, va.y, o[3][1]);
            o[3][2] = fmaf(p3, va.z, o[3][2]); o[3][3] = fmaf(p3, va.w, o[3][3]);
            o[3][4] = fmaf(p3, vb.x, o[3][4]); o[3][5] = fmaf(p3, vb.y, o[3][5]);
            o[3][6] = fmaf(p3, vb.z, o[3][6]); o[3][7] = fmaf(p3, vb.w, o[3][7]);
        }
        __syncthreads();   // PV reads of Vs done before next K-tile load
    }

    // normalize + store ctx
#pragma unroll
    for (int i = 0; i < 4; i++) {
        float inv = 1.0f / l_i[i];
        int   r   = q0 + tr * 4 + i;
        float4 oa, ob;
        oa.x = o[i][0] * inv; oa.y = o[i][1] * inv;
        oa.z = o[i][2] * inv; oa.w = o[i][3] * inv;
        ob.x = o[i][4] * inv; ob.y = o[i][5] * inv;
        ob.z = o[i][6] * inv; ob.w = o[i][7] * inv;
        *(float4*)&O[base + (size_t)r * DMODEL + tc * 8]     = oa;
        *(float4*)&O[base + (size_t)r * DMODEL + tc * 8 + 4] = ob;
    }
}

// -------------------- launch ----------------------------------------------
extern "C" void kernel_launch(void* const* d_in, const int* in_sizes, int n_in,
                              void* d_out, int out_size)
{
    const float* x  = (const float*)d_in[0];
    const float* wq = (const float*)d_in[1];
    const float* wk = (const float*)d_in[2];
    const float* wv = (const float*)d_in[3];
    const float* wo = (const float*)d_in[4];
    float* out = (float*)d_out;

    float *q, *k, *v, *ctx;
    cudaGetSymbolAddress((void**)&q,   g_q);
    cudaGetSymbolAddress((void**)&k,   g_k);
    cudaGetSymbolAddress((void**)&v,   g_v);
    cudaGetSymbolAddress((void**)&ctx, g_ctx);

    // 1) RoPE tables
    rope_table_kernel<<<(SEQ * HALF_D) / 1024, 1024>>>();

    // 2) Q/K/V projections (RoPE fused for Q, K)
    dim3 gg(MROWS / BM, DMODEL / BN);
    gemm128_kernel<<<gg, 256>>>(x, wq, q, 1);
    gemm128_kernel<<<gg, 256>>>(x, wk, k, 1);
    gemm128_kernel<<<gg, 256>>>(x, wv, v, 0);

    // 3) flash attention
    static int smem_set = 0;
    (void)smem_set;
    cudaFuncSetAttribute(flash_kernel,
                         cudaFuncAttributeMaxDynamicSharedMemorySize,
                         SM_FLOATS * sizeof(float));
    flash_kernel<<<dim3(SEQ / BQ, NHEAD, BATCH), 256, SM_FLOATS * sizeof(float)>>>(q, k, v, ctx);

    // 4) output projection
    gemm128_kernel<<<gg, 256>>>(ctx, wo, out, 0);
}

// round 4
// speedup vs baseline: 1.8635x; 1.8635x over previous
#include <cuda_runtime.h>
#include <cuda_bf16.h>
#include <math.h>

// ------------------------------------------------------------------ constants
#define BATCH   8
#define SEQ     1024
#define DMODEL  2048
#define NHEAD   16
#define HEADDIM 128
#define MROWS   (BATCH * SEQ)          // 8192
#define HALF_D  (DMODEL / 2)           // 1024
#define SCALE   0.02209708691207961f   // 1/sqrt(2048)

// ------------------------------------------------------------------ scratch
__device__ float g_q  [MROWS * DMODEL];
__device__ float g_k  [MROWS * DMODEL];
__device__ float g_v  [MROWS * DMODEL];
__device__ float g_ctx[MROWS * DMODEL];
__device__ float g_cos[SEQ * HALF_D];
__device__ float g_sin[SEQ * HALF_D];

__device__ __nv_bfloat16 g_xh[MROWS * DMODEL];
__device__ __nv_bfloat16 g_xl[MROWS * DMODEL];
__device__ __nv_bfloat16 g_ch[MROWS * DMODEL];
__device__ __nv_bfloat16 g_cl[MROWS * DMODEL];
__device__ __nv_bfloat16 g_wqh[DMODEL * DMODEL];
__device__ __nv_bfloat16 g_wql[DMODEL * DMODEL];
__device__ __nv_bfloat16 g_wkh[DMODEL * DMODEL];
__device__ __nv_bfloat16 g_wkl[DMODEL * DMODEL];
__device__ __nv_bfloat16 g_wvh[DMODEL * DMODEL];
__device__ __nv_bfloat16 g_wvl[DMODEL * DMODEL];
__device__ __nv_bfloat16 g_woh[DMODEL * DMODEL];
__device__ __nv_bfloat16 g_wol[DMODEL * DMODEL];

// ------------------------------------------------------------------ PTX helpers
static __device__ __forceinline__ unsigned smem_u32(const void* p) {
    unsigned a;
    asm("{ .reg .u64 t; cvta.to.shared.u64 t, %1; cvt.u32.u64 %0, t; }" : "=r"(a) : "l"(p));
    return a;
}

static __device__ __forceinline__ void cp16(unsigned dst, const void* src) {
    asm volatile("cp.async.cg.shared.global [%0], [%1], 16;" :: "r"(dst), "l"(src));
}
#define CP_COMMIT()  asm volatile("cp.async.commit_group;" ::: "memory")
#define CP_WAIT0()   asm volatile("cp.async.wait_group 0;" ::: "memory")
#define CP_WAIT1()   asm volatile("cp.async.wait_group 1;" ::: "memory")

#define LDSM_X4(r, a) \
    asm volatile("ldmatrix.sync.aligned.m8n8.x4.shared.b16 {%0,%1,%2,%3}, [%4];" \
                 : "=r"((r)[0]), "=r"((r)[1]), "=r"((r)[2]), "=r"((r)[3]) : "r"(a))
#define LDSM_X2(r, a) \
    asm volatile("ldmatrix.sync.aligned.m8n8.x2.shared.b16 {%0,%1}, [%2];" \
                 : "=r"((r)[0]), "=r"((r)[1]) : "r"(a))

#define MMA16816(c, a, b) \
    asm volatile("mma.sync.aligned.m16n8k16.row.col.f32.bf16.bf16.f32 " \
                 "{%0,%1,%2,%3},{%4,%5,%6,%7},{%8,%9},{%0,%1,%2,%3};" \
                 : "+f"((c)[0]), "+f"((c)[1]), "+f"((c)[2]), "+f"((c)[3]) \
                 : "r"((a)[0]), "r"((a)[1]), "r"((a)[2]), "r"((a)[3]), \
                   "r"((b)[0]), "r"((b)[1]))

// ------------------------------------------------------------------ RoPE table
__global__ void rope_table_kernel() {
    int idx = blockIdx.x * blockDim.x + threadIdx.x;
    int t = idx >> 10;
    int p = idx & 1023;
    float inv = expf(-(float)p * (9.210340371976184f / 1024.0f));
    float s, c;
    sincosf((float)t * inv, &s, &c);
    g_cos[idx] = c;
    g_sin[idx] = s;
}

// ------------------------------------------------------------------ fp32 -> bf16 hi/lo split
__global__ __launch_bounds__(256)
void split_kernel(const float* __restrict__ src,
                  __nv_bfloat16* __restrict__ hi,
                  __nv_bfloat16* __restrict__ lo)
{
    size_t i = ((size_t)blockIdx.x * 256 + threadIdx.x) * 4;
    float4 a = *(const float4*)(src + i);
    __nv_bfloat16 h0 = __float2bfloat16(a.x);
    __nv_bfloat16 h1 = __float2bfloat16(a.y);
    __nv_bfloat16 h2 = __float2bfloat16(a.z);
    __nv_bfloat16 h3 = __float2bfloat16(a.w);
    __nv_bfloat16 l0 = __float2bfloat16(a.x - __bfloat162float(h0));
    __nv_bfloat16 l1 = __float2bfloat16(a.y - __bfloat162float(h1));
    __nv_bfloat16 l2 = __float2bfloat16(a.z - __bfloat162float(h2));
    __nv_bfloat16 l3 = __float2bfloat16(a.w - __bfloat162float(h3));
    __nv_bfloat162* H = (__nv_bfloat162*)(hi + i);
    __nv_bfloat162* L = (__nv_bfloat162*)(lo + i);
    H[0] = __nv_bfloat162(h0, h1);  H[1] = __nv_bfloat162(h2, h3);
    L[0] = __nv_bfloat162(l0, l1);  L[1] = __nv_bfloat162(l2, l3);
}

// ------------------------------------------------------------------ mma.sync GEMM
// C[m,n] = sum_k A[m,k]*W[n,k], bf16 hi/lo 3-pass, fp32 accumulate.
// 128x128 CTA tile, BK=64 (128B rows, chunk^row swizzle), 8 warps (2x4),
// each warp 64x32, double-buffered cp.async.
#define TILE_B   16384             // one 128x64 bf16 tile (128B rows)
#define STAGE_B  (4 * TILE_B)      // Ah, Al, Bh, Bl
#define MM_SMEM  (2 * STAGE_B)     // 131072 B
#define NCHUNK   (DMODEL / 64)     // 32

static __device__ __forceinline__ void load_tiles(
    unsigned sbuf,
    const __nv_bfloat16* __restrict__ Ah, const __nv_bfloat16* __restrict__ Al,
    const __nv_bfloat16* __restrict__ Bh, const __nv_bfloat16* __restrict__ Bl,
    int m0, int n0, int k0, int tid)
{
#pragma unroll
    for (int it = 0; it < 4; it++) {
        int i   = tid + it * 256;           // 0..1023
        int row = i >> 3;
        int c   = i & 7;
        unsigned off = (unsigned)(row * 128) + (unsigned)(((c ^ (row & 7)) << 4));
        size_t aoff = (size_t)(m0 + row) * DMODEL + k0 + c * 8;
        size_t boff = (size_t)(n0 + row) * DMODEL + k0 + c * 8;
        cp16(sbuf + 0 * TILE_B + off, Ah + aoff);
        cp16(sbuf + 1 * TILE_B + off, Al + aoff);
        cp16(sbuf + 2 * TILE_B + off, Bh + boff);
        cp16(sbuf + 3 * TILE_B + off, Bl + boff);
    }
}

__global__ __launch_bounds__(256)
void mm_mma_kernel(const __nv_bfloat16* __restrict__ Ah, const __nv_bfloat16* __restrict__ Al,
                   const __nv_bfloat16* __restrict__ Bh, const __nv_bfloat16* __restrict__ Bl,
                   float* __restrict__ C, int rope)
{
    extern __shared__ char smem[];
    const unsigned sb = smem_u32(smem);
    const int tid  = threadIdx.x;
    const int lane = tid & 31;
    const int wid  = tid >> 5;
    const int m0   = blockIdx.x * 128;
    const int n0   = blockIdx.y * 128;
    const int wm   = (wid >> 2) * 64;     // warp M offset (0 or 64)
    const int wn   = (wid & 3) * 32;      // warp N offset (0,32,64,96)

    float acc[4][4][4];
#pragma unroll
    for (int i = 0; i < 4; i++)
#pragma unroll
        for (int j = 0; j < 4; j++)
#pragma unroll
            for (int r = 0; r < 4; r++) acc[i][j][r] = 0.f;

    // ldmatrix per-lane addressing components
    const int      lane7 = lane & 7;
    const unsigned swx   = (unsigned)(lane7 << 4);   // row&7 == lane&7 for all our rows
    const int      ach   = lane >> 4;                // A chunk add (0/1)
    const int      bch   = (lane >> 3) & 1;          // B chunk add (0/1)
    unsigned rA[4], rB[4];
#pragma unroll
    for (int i = 0; i < 4; i++) rA[i] = (unsigned)((wm + i * 16 + (lane & 15)) * 128);
#pragma unroll
    for (int j = 0; j < 4; j++) rB[j] = (unsigned)((wn + j * 8 + lane7) * 128);

    // prologue
    load_tiles(sb, Ah, Al, Bh, Bl, m0, n0, 0, tid);
    CP_COMMIT();

    for (int kc = 0; kc < NCHUNK; ++kc) {
        const int cur = kc & 1;
        if (kc + 1 < NCHUNK) {
            load_tiles(sb + ((kc + 1) & 1) * STAGE_B, Ah, Al, Bh, Bl,
                       m0, n0, (kc + 1) * 64, tid);
            CP_COMMIT();
            CP_WAIT1();
        } else {
            CP_WAIT0();
        }
        __syncthreads();

        const unsigned stage = sb + cur * STAGE_B;
        const unsigned bAh = stage + 0 * TILE_B;
        const unsigned bAl = stage + 1 * TILE_B;
        const unsigned bBh = stage + 2 * TILE_B;
        const unsigned bBl = stage + 3 * TILE_B;

#pragma unroll
        for (int s = 0; s < 4; s++) {
            const unsigned axor = ((unsigned)((2 * s + ach) << 4)) ^ swx;
            const unsigned bxor = ((unsigned)((2 * s + bch) << 4)) ^ swx;
            unsigned ah[4][4], al[4][4], bh[4][2], bl[4][2];
#pragma unroll
            for (int i = 0; i < 4; i++) {
                LDSM_X4(ah[i], bAh + rA[i] + axor);
                LDSM_X4(al[i], bAl + rA[i] + axor);
            }
#pragma unroll
            for (int j = 0; j < 4; j++) {
                LDSM_X2(bh[j], bBh + rB[j] + bxor);
                LDSM_X2(bl[j], bBl + rB[j] + bxor);
            }
#pragma unroll
            for (int i = 0; i < 4; i++)
#pragma unroll
                for (int j = 0; j < 4; j++) {
                    MMA16816(acc[i][j], ah[i], bh[j]);
                    MMA16816(acc[i][j], ah[i], bl[j]);
                    MMA16816(acc[i][j], al[i], bh[j]);
                }
        }
        __syncthreads();
    }

    // epilogue: RoPE in registers, direct float2 stores
#pragma unroll
    for (int i = 0; i < 4; i++) {
        const int gm  = m0 + wm + i * 16 + (lane >> 2);
        const int gm2 = gm + 8;
        const int t   = gm  & (SEQ - 1);
        const int t2  = gm2 & (SEQ - 1);
#pragma unroll
        for (int j = 0; j < 4; j++) {
            const int nG = n0 + wn + j * 8 + 2 * (lane & 3);
            float v0 = acc[i][j][0], v1 = acc[i][j][1];
            float v2 = acc[i][j][2], v3 = acc[i][j][3];
            if (rope) {
                const int p = nG >> 1;
                float c0 = g_cos[t  * HALF_D + p], s0 = g_sin[t  * HALF_D + p];
                float c1 = g_cos[t2 * HALF_D + p], s1 = g_sin[t2 * HALF_D + p];
                float o0 = v0 * c0 - v1 * s0;
                float o1 = v0 * s0 + v1 * c0;
                float o2 = v2 * c1 - v3 * s1;
                float o3 = v2 * s1 + v3 * c1;
                v0 = o0; v1 = o1; v2 = o2; v3 = o3;
            }
            *(float2*)&C[(size_t)gm  * DMODEL + nG] = make_float2(v0, v1);
            *(float2*)&C[(size_t)gm2 * DMODEL + nG] = make_float2(v2, v3);
        }
    }
}

// ------------------------------------------------------------------ flash attention (fp32 SIMT)
#define BQ  64
#define BKV 64
#define QT_STRIDE 65
#define SM_QT 0
#define SM_KV (HEADDIM * QT_STRIDE)
#define SM_PS (SM_KV + HEADDIM * QT_STRIDE)
#define SM_FLOATS (SM_PS + BQ * QT_STRIDE)

__global__ __launch_bounds__(256, 2)
void flash_kernel(const float* __restrict__ Q,
                  const float* __restrict__ K,
                  const float* __restrict__ V,
                  float* __restrict__ O)
{
    extern __shared__ float sm[];
    float* Qt = sm + SM_QT;
    float* KV = sm + SM_KV;
    float* Ps = sm + SM_PS;

    const int tid = threadIdx.x;
    const int tc  = tid & 15;
    const int tr  = tid >> 4;
    const int q0  = blockIdx.x * BQ;
    const int h   = blockIdx.y;
    const int b   = blockIdx.z;
    const size_t base = (size_t)b * SEQ * DMODEL + (size_t)h * HEADDIM;

    for (int idx = tid; idx < BQ * (HEADDIM / 4); idx += 256) {
        int row = idx >> 5;
        int kv  = idx & 31;
        float4 v = *(const float4*)&Q[base + (size_t)(q0 + row) * DMODEL + kv * 4];
        Qt[(kv * 4 + 0) * QT_STRIDE + row] = v.x * SCALE;
        Qt[(kv * 4 + 1) * QT_STRIDE + row] = v.y * SCALE;
        Qt[(kv * 4 + 2) * QT_STRIDE + row] = v.z * SCALE;
        Qt[(kv * 4 + 3) * QT_STRIDE + row] = v.w * SCALE;
    }

    float m_i[4], l_i[4], o[4][8];
#pragma unroll
    for (int i = 0; i < 4; i++) {
        m_i[i] = -1e30f; l_i[i] = 0.f;
#pragma unroll
        for (int j = 0; j < 8; j++) o[i][j] = 0.f;
    }
    __syncthreads();

    for (int kt = 0; kt < SEQ / BKV; kt++) {
        const int k0 = kt * BKV;

        for (int idx = tid; idx < BKV * (HEADDIM / 4); idx += 256) {
            int row = idx >> 5;
            int kv  = idx & 31;
            float4 v = *(const float4*)&K[base + (size_t)(k0 + row) * DMODEL + kv * 4];
            KV[(kv * 4 + 0) * QT_STRIDE + row] = v.x;
            KV[(kv * 4 + 1) * QT_STRIDE + row] = v.y;
            KV[(kv * 4 + 2) * QT_STRIDE + row] = v.z;
            KV[(kv * 4 + 3) * QT_STRIDE + row] = v.w;
        }
        __syncthreads();

        float s[4][4];
#pragma unroll
        for (int i = 0; i < 4; i++)
#pragma unroll
            for (int j = 0; j < 4; j++) s[i][j] = 0.f;

#pragma unroll 4
        for (int kk = 0; kk < HEADDIM; kk++) {
            float a0 = Qt[kk * QT_STRIDE + tr * 4 + 0];
            float a1 = Qt[kk * QT_STRIDE + tr * 4 + 1];
            float a2 = Qt[kk * QT_STRIDE + tr * 4 + 2];
            float a3 = Qt[kk * QT_STRIDE + tr * 4 + 3];
            float b0 = KV[kk * QT_STRIDE + tc * 4 + 0];
            float b1 = KV[kk * QT_STRIDE + tc * 4 + 1];
            float b2 = KV[kk * QT_STRIDE + tc * 4 + 2];
            float b3 = KV[kk * QT_STRIDE + tc * 4 + 3];
            s[0][0] = fmaf(a0, b0, s[0][0]); s[0][1] = fmaf(a0, b1, s[0][1]);
            s[0][2] = fmaf(a0, b2, s[0][2]); s[0][3] = fmaf(a0, b3, s[0][3]);
            s[1][0] = fmaf(a1, b0, s[1][0]); s[1][1] = fmaf(a1, b1, s[1][1]);
            s[1][2] = fmaf(a1, b2, s[1][2]); s[1][3] = fmaf(a1, b3, s[1][3]);
            s[2][0] = fmaf(a2, b0, s[2][0]); s[2][1] = fmaf(a2, b1, s[2][1]);
            s[2][2] = fmaf(a2, b2, s[2][2]); s[2][3] = fmaf(a2, b3, s[2][3]);
            s[3][0] = fmaf(a3, b0, s[3][0]); s[3][1] = fmaf(a3, b1, s[3][1]);
            s[3][2] = fmaf(a3, b2, s[3][2]); s[3][3] = fmaf(a3, b3, s[3][3]);
        }

#pragma unroll
        for (int i = 0; i < 4; i++) {
            float mx = fmaxf(fmaxf(s[i][0], s[i][1]), fmaxf(s[i][2], s[i][3]));
#pragma unroll
            for (int off = 1; off < 16; off <<= 1)
                mx = fmaxf(mx, __shfl_xor_sync(0xffffffffu, mx, off));
            float mnew  = fmaxf(m_i[i], mx);
            float alpha = __expf(m_i[i] - mnew);
            m_i[i] = mnew;
            float rs = 0.f;
#pragma unroll
            for (int j = 0; j < 4; j++) { s[i][j] = __expf(s[i][j] - mnew); rs += s[i][j]; }
#pragma unroll
            for (int off = 1; off < 16; off <<= 1)
                rs += __shfl_xor_sync(0xffffffffu, rs, off);
            l_i[i] = l_i[i] * alpha + rs;
#pragma unroll
            for (int j = 0; j < 8; j++) o[i][j] *= alpha;
        }
        __syncthreads();

#pragma unroll
        for (int i = 0; i < 4; i++)
#pragma unroll
            for (int j = 0; j < 4; j++)
                Ps[(tr * 4 + i) * QT_STRIDE + tc * 4 + j] = s[i][j];

        for (int idx = tid; idx < BKV * (HEADDIM / 4); idx += 256) {
            int row = idx >> 5;
            int kv  = idx & 31;
            float4 v = *(const float4*)&V[base + (size_t)(k0 + row) * DMODEL + kv * 4];
            *(float4*)&KV[row * HEADDIM + kv * 4] = v;
        }
        __syncthreads();

#pragma unroll 2
        for (int kk = 0; kk < BKV; kk++) {
            float p0 = Ps[(tr * 4 + 0) * QT_STRIDE + kk];
            float p1 = Ps[(tr * 4 + 1) * QT_STRIDE + kk];
            float p2 = Ps[(tr * 4 + 2) * QT_STRIDE + kk];
            float p3 = Ps[(tr * 4 + 3) * QT_STRIDE + kk];
            float4 va = *(const float4*)&KV[kk * HEADDIM + tc * 8];
            float4 vb = *(const float4*)&KV[kk * HEADDIM + tc * 8 + 4];
            o[0][0] = fmaf(p0, va.x, o[0][0]); o[0][1] = fmaf(p0, va.y, o[0][1]);
            o[0][2] = fmaf(p0, va.z, o[0][2]); o[0][3] = fmaf(p0, va.w, o[0][3]);
            o[0][4] = fmaf(p0, vb.x, o[0][4]); o[0][5] = fmaf(p0, vb.y, o[0][5]);
            o[0][6] = fmaf(p0, vb.z, o[0][6]); o[0][7] = fmaf(p0, vb.w, o[0][7]);
            o[1][0] = fmaf(p1, va.x, o[1][0]); o[1][1] = fmaf(p1, va.y, o[1][1]);
            o[1][2] = fmaf(p1, va.z, o[1][2]); o[1][3] = fmaf(p1, va.w, o[1][3]);
            o[1][4] = fmaf(p1, vb.x, o[1][4]); o[1][5] = fmaf(p1, vb.y, o[1][5]);
            o[1][6] = fmaf(p1, vb.z, o[1][6]); o[1][7] = fmaf(p1, vb.w, o[1][7]);
            o[2][0] = fmaf(p2, va.x, o[2][0]); o[2][1] = fmaf(p2, va.y, o[2][1]);
            o[2][2] = fmaf(p2, va.z, o[2][2]); o[2][3] = fmaf(p2, va.w, o[2][3]);
            o[2][4] = fmaf(p2, vb.x, o[2][4]); o[2][5] = fmaf(p2, vb.y, o[2][5]);
            o[2][6] = fmaf(p2, vb.z, o[2][6]); o[2][7] = fmaf(p2, vb.w, o[2][7]);
            o[3][0] = fmaf(p3, va.x, o[3][0]); o[3][1] = fmaf(p3, va.y, o[3][1]);
            o[3][2] = fmaf(p3, va.z, o[3][2]); o[3][3] = fmaf(p3, va.w, o[3][3]);
            o[3][4] = fmaf(p3, vb.x, o[3][4]); o[3][5] = fmaf(p3, vb.y, o[3][5]);
            o[3][6] = fmaf(p3, vb.z, o[3][6]); o[3][7] = fmaf(p3, vb.w, o[3][7]);
        }
        __syncthreads();
    }

#pragma unroll
    for (int i = 0; i < 4; i++) {
        float inv = 1.0f / l_i[i];
        int   r   = q0 + tr * 4 + i;
        float4 oa, ob;
        oa.x = o[i][0] * inv; oa.y = o[i][1] * inv;
        oa.z = o[i][2] * inv; oa.w = o[i][3] * inv;
        ob.x = o[i][4] * inv; ob.y = o[i][5] * inv;
        ob.z = o[i][6] * inv; ob.w = o[i][7] * inv;
        *(float4*)&O[base + (size_t)r * DMODEL + tc * 8]     = oa;
        *(float4*)&O[base + (size_t)r * DMODEL + tc * 8 + 4] = ob;
    }
}

// ------------------------------------------------------------------ launch
extern "C" void kernel_launch(void* const* d_in, const int* in_sizes, int n_in,
                              void* d_out, int out_size)
{
    const float* x  = (const float*)d_in[0];
    const float* wq = (const float*)d_in[1];
    const float* wk = (const float*)d_in[2];
    const float* wv = (const float*)d_in[3];
    const float* wo = (const float*)d_in[4];
    float* out = (float*)d_out;

    float *q, *k, *v, *ctx;
    cudaGetSymbolAddress((void**)&q,   g_q);
    cudaGetSymbolAddress((void**)&k,   g_k);
    cudaGetSymbolAddress((void**)&v,   g_v);
    cudaGetSymbolAddress((void**)&ctx, g_ctx);
    __nv_bfloat16 *xh, *xl, *ch, *cl, *wqh, *wql, *wkh, *wkl, *wvh, *wvl, *woh, *wol;
    cudaGetSymbolAddress((void**)&xh, g_xh);   cudaGetSymbolAddress((void**)&xl, g_xl);
    cudaGetSymbolAddress((void**)&ch, g_ch);   cudaGetSymbolAddress((void**)&cl, g_cl);
    cudaGetSymbolAddress((void**)&wqh, g_wqh); cudaGetSymbolAddress((void**)&wql, g_wql);
    cudaGetSymbolAddress((void**)&wkh, g_wkh); cudaGetSymbolAddress((void**)&wkl, g_wkl);
    cudaGetSymbolAddress((void**)&wvh, g_wvh); cudaGetSymbolAddress((void**)&wvl, g_wvl);
    cudaGetSymbolAddress((void**)&woh, g_woh); cudaGetSymbolAddress((void**)&wol, g_wol);

    cudaFuncSetAttribute(mm_mma_kernel, cudaFuncAttributeMaxDynamicSharedMemorySize, MM_SMEM);
    cudaFuncSetAttribute(flash_kernel, cudaFuncAttributeMaxDynamicSharedMemorySize,
                         SM_FLOATS * sizeof(float));

    // 1) RoPE tables + splits
    rope_table_kernel<<<(SEQ * HALF_D) / 1024, 1024>>>();
    split_kernel<<<(MROWS * DMODEL) / 1024, 256>>>(x, xh, xl);
    split_kernel<<<(DMODEL * DMODEL) / 1024, 256>>>(wq, wqh, wql);
    split_kernel<<<(DMODEL * DMODEL) / 1024, 256>>>(wk, wkh, wkl);
    split_kernel<<<(DMODEL * DMODEL) / 1024, 256>>>(wv, wvh, wvl);
    split_kernel<<<(DMODEL * DMODEL) / 1024, 256>>>(wo, woh, wol);

    // 2) projections on tensor cores (RoPE fused for Q/K)
    dim3 gg(MROWS / 128, DMODEL / 128);
    mm_mma_kernel<<<gg, 256, MM_SMEM>>>(xh, xl, wqh, wql, q, 1);
    mm_mma_kernel<<<gg, 256, MM_SMEM>>>(xh, xl, wkh, wkl, k, 1);
    mm_mma_kernel<<<gg, 256, MM_SMEM>>>(xh, xl, wvh, wvl, v, 0);

    // 3) flash attention (fp32 SIMT)
    flash_kernel<<<dim3(SEQ / BQ, NHEAD, BATCH), 256, SM_FLOATS * sizeof(float)>>>(q, k, v, ctx);

    // 4) output projection
    split_kernel<<<(MROWS * DMODEL) / 1024, 256>>>(ctx, ch, cl);
    mm_mma_kernel<<<gg, 256, MM_SMEM>>>(ch, cl, woh, wol, out, 0);
}

// round 5
// speedup vs baseline: 3.2117x; 1.7235x over previous
#include <cuda_runtime.h>
#include <cuda_bf16.h>
#include <math.h>

// ------------------------------------------------------------------ constants
#define BATCH   8
#define SEQ     1024
#define DMODEL  2048
#define NHEAD   16
#define HEADDIM 128
#define MROWS   (BATCH * SEQ)          // 8192
#define HALF_D  (DMODEL / 2)           // 1024
#define SCALE   0.02209708691207961f   // 1/sqrt(2048)

// ------------------------------------------------------------------ scratch (bf16 hi/lo everywhere)
__device__ float g_cos[SEQ * HALF_D];
__device__ float g_sin[SEQ * HALF_D];

__device__ __nv_bfloat16 g_xh[MROWS * DMODEL];
__device__ __nv_bfloat16 g_xl[MROWS * DMODEL];
__device__ __nv_bfloat16 g_qh[MROWS * DMODEL];
__device__ __nv_bfloat16 g_ql[MROWS * DMODEL];
__device__ __nv_bfloat16 g_kh[MROWS * DMODEL];
__device__ __nv_bfloat16 g_kl[MROWS * DMODEL];
__device__ __nv_bfloat16 g_vh[MROWS * DMODEL];
__device__ __nv_bfloat16 g_vl[MROWS * DMODEL];
__device__ __nv_bfloat16 g_ch[MROWS * DMODEL];
__device__ __nv_bfloat16 g_cl[MROWS * DMODEL];
__device__ __nv_bfloat16 g_wqh[DMODEL * DMODEL];
__device__ __nv_bfloat16 g_wql[DMODEL * DMODEL];
__device__ __nv_bfloat16 g_wkh[DMODEL * DMODEL];
__device__ __nv_bfloat16 g_wkl[DMODEL * DMODEL];
__device__ __nv_bfloat16 g_wvh[DMODEL * DMODEL];
__device__ __nv_bfloat16 g_wvl[DMODEL * DMODEL];
__device__ __nv_bfloat16 g_woh[DMODEL * DMODEL];
__device__ __nv_bfloat16 g_wol[DMODEL * DMODEL];

// ------------------------------------------------------------------ PTX helpers
static __device__ __forceinline__ unsigned smem_u32(const void* p) {
    unsigned a;
    asm("{ .reg .u64 t; cvta.to.shared.u64 t, %1; cvt.u32.u64 %0, t; }" : "=r"(a) : "l"(p));
    return a;
}
static __device__ __forceinline__ void cp16(unsigned dst, const void* src) {
    asm volatile("cp.async.cg.shared.global [%0], [%1], 16;" :: "r"(dst), "l"(src));
}
#define CP_COMMIT()  asm volatile("cp.async.commit_group;" ::: "memory")
#define CP_WAIT0()   asm volatile("cp.async.wait_group 0;" ::: "memory")
#define CP_WAIT1()   asm volatile("cp.async.wait_group 1;" ::: "memory")

#define LDSM_X4(r, a) \
    asm volatile("ldmatrix.sync.aligned.m8n8.x4.shared.b16 {%0,%1,%2,%3}, [%4];" \
                 : "=r"((r)[0]), "=r"((r)[1]), "=r"((r)[2]), "=r"((r)[3]) : "r"(a))
#define LDSM_X4_T(r, a) \
    asm volatile("ldmatrix.sync.aligned.m8n8.x4.trans.shared.b16 {%0,%1,%2,%3}, [%4];" \
                 : "=r"((r)[0]), "=r"((r)[1]), "=r"((r)[2]), "=r"((r)[3]) : "r"(a))
#define LDSM_X2(r, a) \
    asm volatile("ldmatrix.sync.aligned.m8n8.x2.shared.b16 {%0,%1}, [%2];" \
                 : "=r"((r)[0]), "=r"((r)[1]) : "r"(a))

#define MMA16816(c, a, b) \
    asm volatile("mma.sync.aligned.m16n8k16.row.col.f32.bf16.bf16.f32 " \
                 "{%0,%1,%2,%3},{%4,%5,%6,%7},{%8,%9},{%0,%1,%2,%3};" \
                 : "+f"((c)[0]), "+f"((c)[1]), "+f"((c)[2]), "+f"((c)[3]) \
                 : "r"((a)[0]), "r"((a)[1]), "r"((a)[2]), "r"((a)[3]), \
                   "r"((b)[0]), "r"((b)[1]))
#define MMA2(c, a, b0v, b1v) \
    asm volatile("mma.sync.aligned.m16n8k16.row.col.f32.bf16.bf16.f32 " \
                 "{%0,%1,%2,%3},{%4,%5,%6,%7},{%8,%9},{%0,%1,%2,%3};" \
                 : "+f"((c)[0]), "+f"((c)[1]), "+f"((c)[2]), "+f"((c)[3]) \
                 : "r"((a)[0]), "r"((a)[1]), "r"((a)[2]), "r"((a)[3]), \
                   "r"(b0v), "r"(b1v))

static __device__ __forceinline__ void split2(float x, float y, unsigned &h, unsigned &l) {
    __nv_bfloat162 hb = __floats2bfloat162_rn(x, y);
    float hx = __low2float(hb), hy = __high2float(hb);
    __nv_bfloat162 lb = __floats2bfloat162_rn(x - hx, y - hy);
    h = *reinterpret_cast<unsigned*>(&hb);
    l = *reinterpret_cast<unsigned*>(&lb);
}

// ------------------------------------------------------------------ RoPE table
__global__ void rope_table_kernel() {
    int idx = blockIdx.x * blockDim.x + threadIdx.x;
    int t = idx >> 10;
    int p = idx & 1023;
    float inv = expf(-(float)p * (9.210340371976184f / 1024.0f));
    float s, c;
    sincosf((float)t * inv, &s, &c);
    g_cos[idx] = c;
    g_sin[idx] = s;
}

// ------------------------------------------------------------------ fp32 -> bf16 hi/lo split
__global__ __launch_bounds__(256)
void split_kernel(const float* __restrict__ src,
                  __nv_bfloat16* __restrict__ hi,
                  __nv_bfloat16* __restrict__ lo)
{
    size_t i = ((size_t)blockIdx.x * 256 + threadIdx.x) * 4;
    float4 a = *(const float4*)(src + i);
    unsigned h0, l0, h1, l1;
    split2(a.x, a.y, h0, l0);
    split2(a.z, a.w, h1, l1);
    unsigned* H = (unsigned*)(hi + i);
    unsigned* L = (unsigned*)(lo + i);
    H[0] = h0; H[1] = h1;
    L[0] = l0; L[1] = l1;
}

// ------------------------------------------------------------------ mma.sync GEMM (bf16 hi/lo 3-pass)
// C = A @ W^T. Output: fp32 (Cf) OR bf16 hi/lo (Chi/Clo) with optional RoPE+scale.
#define TILE_B   16384             // one 128x64 bf16 tile (128B rows)
#define STAGE_B  (4 * TILE_B)
#define MM_SMEM  (2 * STAGE_B)     // 131072 B
#define NCHUNK   (DMODEL / 64)     // 32

static __device__ __forceinline__ void load_tiles(
    unsigned sbuf,
    const __nv_bfloat16* __restrict__ Ah, const __nv_bfloat16* __restrict__ Al,
    const __nv_bfloat16* __restrict__ Bh, const __nv_bfloat16* __restrict__ Bl,
    int m0, int n0, int k0, int tid)
{
#pragma unroll
    for (int it = 0; it < 4; it++) {
        int i   = tid + it * 256;
        int row = i >> 3;
        int c   = i & 7;
        unsigned off = (unsigned)(row * 128) + (unsigned)(((c ^ (row & 7)) << 4));
        size_t aoff = (size_t)(m0 + row) * DMODEL + k0 + c * 8;
        size_t boff = (size_t)(n0 + row) * DMODEL + k0 + c * 8;
        cp16(sbuf + 0 * TILE_B + off, Ah + aoff);
        cp16(sbuf + 1 * TILE_B + off, Al + aoff);
        cp16(sbuf + 2 * TILE_B + off, Bh + boff);
        cp16(sbuf + 3 * TILE_B + off, Bl + boff);
    }
}

__global__ __launch_bounds__(256)
void mm_mma_kernel(const __nv_bfloat16* __restrict__ Ah, const __nv_bfloat16* __restrict__ Al,
                   const __nv_bfloat16* __restrict__ Bh, const __nv_bfloat16* __restrict__ Bl,
                   float* __restrict__ Cf,
                   __nv_bfloat16* __restrict__ Chi, __nv_bfloat16* __restrict__ Clo,
                   int rope, float scale)
{
    extern __shared__ char smem[];
    const unsigned sb = smem_u32(smem);
    const int tid  = threadIdx.x;
    const int lane = tid & 31;
    const int wid  = tid >> 5;
    const int m0   = blockIdx.x * 128;
    const int n0   = blockIdx.y * 128;
    const int wm   = (wid >> 2) * 64;
    const int wn   = (wid & 3) * 32;

    float acc[4][4][4];
#pragma unroll
    for (int i = 0; i < 4; i++)
#pragma unroll
        for (int j = 0; j < 4; j++)
#pragma unroll
            for (int r = 0; r < 4; r++) acc[i][j][r] = 0.f;

    const int      lane7 = lane & 7;
    const unsigned swx   = (unsigned)(lane7 << 4);
    const int      ach   = lane >> 4;
    const int      bch   = (lane >> 3) & 1;
    unsigned rA[4], rB[4];
#pragma unroll
    for (int i = 0; i < 4; i++) rA[i] = (unsigned)((wm + i * 16 + (lane & 15)) * 128);
#pragma unroll
    for (int j = 0; j < 4; j++) rB[j] = (unsigned)((wn + j * 8 + lane7) * 128);

    load_tiles(sb, Ah, Al, Bh, Bl, m0, n0, 0, tid);
    CP_COMMIT();

    for (int kc = 0; kc < NCHUNK; ++kc) {
        const int cur = kc & 1;
        if (kc + 1 < NCHUNK) {
            load_tiles(sb + ((kc + 1) & 1) * STAGE_B, Ah, Al, Bh, Bl,
                       m0, n0, (kc + 1) * 64, tid);
            CP_COMMIT();
            CP_WAIT1();
        } else {
            CP_WAIT0();
        }
        __syncthreads();

        const unsigned stage = sb + cur * STAGE_B;
        const unsigned bAh = stage + 0 * TILE_B;
        const unsigned bAl = stage + 1 * TILE_B;
        const unsigned bBh = stage + 2 * TILE_B;
        const unsigned bBl = stage + 3 * TILE_B;

#pragma unroll
        for (int s = 0; s < 4; s++) {
            const unsigned axor = ((unsigned)((2 * s + ach) << 4)) ^ swx;
            const unsigned bxor = ((unsigned)((2 * s + bch) << 4)) ^ swx;
            unsigned ah[4][4], al[4][4], bh[4][2], bl[4][2];
#pragma unroll
            for (int i = 0; i < 4; i++) {
                LDSM_X4(ah[i], bAh + rA[i] + axor);
                LDSM_X4(al[i], bAl + rA[i] + axor);
            }
#pragma unroll
            for (int j = 0; j < 4; j++) {
                LDSM_X2(bh[j], bBh + rB[j] + bxor);
                LDSM_X2(bl[j], bBl + rB[j] + bxor);
            }
#pragma unroll
            for (int i = 0; i < 4; i++)
#pragma unroll
                for (int j = 0; j < 4; j++) {
                    MMA16816(acc[i][j], ah[i], bh[j]);
                    MMA16816(acc[i][j], ah[i], bl[j]);
                    MMA16816(acc[i][j], al[i], bh[j]);
                }
        }
        __syncthreads();
    }

    // epilogue: optional RoPE + scale, output fp32 or bf16 hi/lo
#pragma unroll
    for (int i = 0; i < 4; i++) {
        const int gm  = m0 + wm + i * 16 + (lane >> 2);
        const int gm2 = gm + 8;
        const int t   = gm  & (SEQ - 1);
        const int t2  = gm2 & (SEQ - 1);
#pragma unroll
        for (int j = 0; j < 4; j++) {
            const int nG = wn + n0 + j * 8 + 2 * (lane & 3);
            float v0 = acc[i][j][0], v1 = acc[i][j][1];
            float v2 = acc[i][j][2], v3 = acc[i][j][3];
            if (rope) {
                const int p = nG >> 1;
                float c0 = g_cos[t  * HALF_D + p], s0 = g_sin[t  * HALF_D + p];
                float c1 = g_cos[t2 * HALF_D + p], s1 = g_sin[t2 * HALF_D + p];
                float o0 = v0 * c0 - v1 * s0;
                float o1 = v0 * s0 + v1 * c0;
                float o2 = v2 * c1 - v3 * s1;
                float o3 = v2 * s1 + v3 * c1;
                v0 = o0; v1 = o1; v2 = o2; v3 = o3;
            }
            v0 *= scale; v1 *= scale; v2 *= scale; v3 *= scale;
            if (Cf) {
                *(float2*)&Cf[(size_t)gm  * DMODEL + nG] = make_float2(v0, v1);
                *(float2*)&Cf[(size_t)gm2 * DMODEL + nG] = make_float2(v2, v3);
            } else {
                unsigned h0, l0, h1, l1;
                split2(v0, v1, h0, l0);
                split2(v2, v3, h1, l1);
                *(unsigned*)&Chi[(size_t)gm  * DMODEL + nG] = h0;
                *(unsigned*)&Clo[(size_t)gm  * DMODEL + nG] = l0;
                *(unsigned*)&Chi[(size_t)gm2 * DMODEL + nG] = h1;
                *(unsigned*)&Clo[(size_t)gm2 * DMODEL + nG] = l1;
            }
        }
    }
}

// ------------------------------------------------------------------ tensor-core flash attention
// CTA: 128 q-rows x one (head, batch); 8 warps x 16 rows. kv tiles of 64.
// smem: Qh|Ql (128x128 bf16, 256B swizzled rows) resident; K/V hi/lo double-buffered.
#define FQ_H   0
#define FQ_L   32768
#define FKV0   65536
#define FSTAGE 65536               // Kh 16K | Kl 16K | Vh 16K | Vl 16K
#define FLASH_SMEM (FKV0 + 2 * FSTAGE)   // 196608 B
#define NKV    (SEQ / 64)          // 16

// load a [rows x 128] bf16 head-slice tile into swizzled smem (256B rows)
static __device__ __forceinline__ void ld_tile(unsigned dst, const __nv_bfloat16* g,
                                               int rows, int tid)
{
    int total = rows * 16;
    for (int i = tid; i < total; i += 256) {
        int row = i >> 4, c = i & 15;
        unsigned off = (unsigned)(row * 256) + (unsigned)((c >> 3) << 7)
                     + (unsigned)((((c & 7) ^ (row & 7)) << 4));
        cp16(dst + off, g + (size_t)row * DMODEL + c * 8);
    }
}

__global__ __launch_bounds__(256, 1)
void flash_mma_kernel(const __nv_bfloat16* __restrict__ gQh, const __nv_bfloat16* __restrict__ gQl,
                      const __nv_bfloat16* __restrict__ gKh, const __nv_bfloat16* __restrict__ gKl,
                      const __nv_bfloat16* __restrict__ gVh, const __nv_bfloat16* __restrict__ gVl,
                      __nv_bfloat16* __restrict__ Ch, __nv_bfloat16* __restrict__ Cl)
{
    extern __shared__ char smem[];
    const unsigned sb = smem_u32(smem);
    const int tid  = threadIdx.x;
    const int lane = tid & 31;
    const int wid  = tid >> 5;
    const int q0   = blockIdx.x * 128;
    const int h    = blockIdx.y;
    const int b    = blockIdx.z;

    const size_t gQ = ((size_t)(b * SEQ + q0)) * DMODEL + h * HEADDIM;
    const size_t gK = ((size_t)(b * SEQ)) * DMODEL + h * HEADDIM;

    // resident Q + first KV stage
    ld_tile(sb + FQ_H, gQh + gQ, 128, tid);
    ld_tile(sb + FQ_L, gQl + gQ, 128, tid);
    {
        unsigned st = sb + FKV0;
        ld_tile(st,         gKh + gK, 64, tid);
        ld_tile(st + 16384, gKl + gK, 64, tid);
        ld_tile(st + 32768, gVh + gK, 64, tid);
        ld_tile(st + 49152, gVl + gK, 64, tid);
    }
    CP_COMMIT();

    float o[16][4];
#pragma unroll
    for (int j = 0; j < 16; j++)
#pragma unroll
        for (int c = 0; c < 4; c++) o[j][c] = 0.f;
    float m0 = -1e30f, m1 = -1e30f, l0 = 0.f, l1 = 0.f;

    // per-lane addressing
    const unsigned sw7   = (unsigned)((lane & 7) << 4);
    const int      rowQ  = wid * 16 + (lane & 15);
    const unsigned aQb   = (unsigned)(rowQ * 256);
    const int      ach   = lane >> 4;                  // A k-chunk add
    const int      bofs  = ((lane >> 4) << 3) + (lane & 7);   // K row offset in n16 block
    const int      bchA  = (lane >> 3) & 1;            // K k-chunk add
    const int      vofs  = (((lane >> 3) & 1) << 3) + (lane & 7); // V row offset in k16
    const int      vchA  = lane >> 4;                  // V n-chunk add

    for (int kt = 0; kt < NKV; kt++) {
        if (kt + 1 < NKV) {
            unsigned st = sb + FKV0 + ((kt + 1) & 1) * FSTAGE;
            size_t   gk = gK + (size_t)(kt + 1) * 64 * DMODEL;
            ld_tile(st,         gKh + gk, 64, tid);
            ld_tile(st + 16384, gKl + gk, 64, tid);
            ld_tile(st + 32768, gVh + gk, 64, tid);
            ld_tile(st + 49152, gVl + gk, 64, tid);
            CP_COMMIT();
            CP_WAIT1();
        } else {
            CP_WAIT0();
        }
        __syncthreads();

        const unsigned stg = sb + FKV0 + (kt & 1) * FSTAGE;
        const unsigned sKh = stg, sVh = stg + 32768;

        // ---- S = Q K^T (3-pass hi/lo); Q pre-scaled by 1/sqrt(d)
        float s[8][4];
#pragma unroll
        for (int j = 0; j < 8; j++)
#pragma unroll
            for (int c = 0; c < 4; c++) s[j][c] = 0.f;

#pragma unroll
        for (int st8 = 0; st8 < 8; st8++) {
            const int      kcA = 2 * st8 + ach;
            const unsigned aoff = aQb + ((unsigned)(kcA >> 3) << 7)
                                + ((((unsigned)(kcA & 7)) << 4) ^ sw7);
            unsigned qh4[4], ql4[4];
            LDSM_X4(qh4, sb + FQ_H + aoff);
            LDSM_X4(ql4, sb + FQ_L + aoff);
#pragma unroll
            for (int j16 = 0; j16 < 4; j16++) {
                const int      rowB = j16 * 16 + bofs;
                const int      kcB  = 2 * st8 + bchA;
                const unsigned boff = (unsigned)(rowB * 256) + ((unsigned)(kcB >> 3) << 7)
                                    + ((((unsigned)(kcB & 7)) << 4) ^ sw7);
                unsigned kh4[4], kl4[4];
                LDSM_X4(kh4, sKh + boff);
                LDSM_X4(kl4, sKh + 16384 + boff);
                MMA2(s[2 * j16],     qh4, kh4[0], kh4[1]);
                MMA2(s[2 * j16],     qh4, kl4[0], kl4[1]);
                MMA2(s[2 * j16],     ql4, kh4[0], kh4[1]);
                MMA2(s[2 * j16 + 1], qh4, kh4[2], kh4[3]);
                MMA2(s[2 * j16 + 1], qh4, kl4[2], kl4[3]);
                MMA2(s[2 * j16 + 1], ql4, kh4[2], kh4[3]);
            }
        }

        // ---- online softmax (rows r = lane>>2 and r+8; quad reduction)
        {
            float mx0 = -1e30f, mx1 = -1e30f;
#pragma unroll
            for (int j = 0; j < 8; j++) {
                mx0 = fmaxf(mx0, fmaxf(s[j][0], s[j][1]));
                mx1 = fmaxf(mx1, fmaxf(s[j][2], s[j][3]));
            }
            mx0 = fmaxf(mx0, __shfl_xor_sync(0xffffffffu, mx0, 1));
            mx0 = fmaxf(mx0, __shfl_xor_sync(0xffffffffu, mx0, 2));
            mx1 = fmaxf(mx1, __shfl_xor_sync(0xffffffffu, mx1, 1));
            mx1 = fmaxf(mx1, __shfl_xor_sync(0xffffffffu, mx1, 2));
            float mn0 = fmaxf(m0, mx0), mn1 = fmaxf(m1, mx1);
            float al0 = __expf(m0 - mn0), al1 = __expf(m1 - mn1);
            m0 = mn0; m1 = mn1;
            float su0 = 0.f, su1 = 0.f;
#pragma unroll
            for (int j = 0; j < 8; j++) {
                s[j][0] = __expf(s[j][0] - mn0);
                s[j][1] = __expf(s[j][1] - mn0);
                s[j][2] = __expf(s[j][2] - mn1);
                s[j][3] = __expf(s[j][3] - mn1);
                su0 += s[j][0] + s[j][1];
                su1 += s[j][2] + s[j][3];
            }
            su0 += __shfl_xor_sync(0xffffffffu, su0, 1);
            su0 += __shfl_xor_sync(0xffffffffu, su0, 2);
            su1 += __shfl_xor_sync(0xffffffffu, su1, 1);
            su1 += __shfl_xor_sync(0xffffffffu, su1, 2);
            l0 = l0 * al0 + su0;
            l1 = l1 * al1 + su1;
#pragma unroll
            for (int j = 0; j < 16; j++) {
                o[j][0] *= al0; o[j][1] *= al0;
                o[j][2] *= al1; o[j][3] *= al1;
            }
        }

        // ---- O += P V (3-pass: Ph*Vh + Ph*Vl + Pl*Vh), P from registers
#pragma unroll
        for (int s4 = 0; s4 < 4; s4++) {
            unsigned pah[4], pal[4];
            split2(s[2 * s4][0],     s[2 * s4][1],     pah[0], pal[0]);
            split2(s[2 * s4][2],     s[2 * s4][3],     pah[1], pal[1]);
            split2(s[2 * s4 + 1][0], s[2 * s4 + 1][1], pah[2], pal[2]);
            split2(s[2 * s4 + 1][2], s[2 * s4 + 1][3], pah[3], pal[3]);
            const int rowV = s4 * 16 + vofs;
#pragma unroll
            for (int j16 = 0; j16 < 8; j16++) {
                const int      kcV  = 2 * j16 + vchA;
                const unsigned voff = (unsigned)(rowV * 256) + ((unsigned)(kcV >> 3) << 7)
                                    + ((((unsigned)(kcV & 7)) << 4) ^ sw7);
                unsigned vh4[4], vl4[4];
                LDSM_X4_T(vh4, sVh + voff);
                LDSM_X4_T(vl4, sVh + 16384 + voff);
                MMA2(o[2 * j16],     pah, vh4[0], vh4[1]);
                MMA2(o[2 * j16],     pah, vl4[0], vl4[1]);
                MMA2(o[2 * j16],     pal, vh4[0], vh4[1]);
                MMA2(o[2 * j16 + 1], pah, vh4[2], vh4[3]);
                MMA2(o[2 * j16 + 1], pah, vl4[2], vl4[3]);
                MMA2(o[2 * j16 + 1], pal, vh4[2], vh4[3]);
            }
        }
        __syncthreads();
    }

    // ---- epilogue: normalize, write ctx directly as bf16 hi/lo
    const float inv0 = 1.0f / l0;
    const float inv1 = 1.0f / l1;
    const int gr0 = q0 + wid * 16 + (lane >> 2);
    const size_t base0 = ((size_t)(b * SEQ) + gr0) * DMODEL + h * HEADDIM;
    const size_t base1 = base0 + (size_t)8 * DMODEL;
#pragma unroll
    for (int j = 0; j < 16; j++) {
        const int col = j * 8 + 2 * (lane & 3);
        unsigned h0, lo0, h1, lo1;
        split2(o[j][0] * inv0, o[j][1] * inv0, h0, lo0);
        split2(o[j][2] * inv1, o[j][3] * inv1, h1, lo1);
        *(unsigned*)&Ch[base0 + col] = h0;
        *(unsigned*)&Cl[base0 + col] = lo0;
        *(unsigned*)&Ch[base1 + col] = h1;
        *(unsigned*)&Cl[base1 + col] = lo1;
    }
}

// ------------------------------------------------------------------ launch
extern "C" void kernel_launch(void* const* d_in, const int* in_sizes, int n_in,
                              void* d_out, int out_size)
{
    const float* x  = (const float*)d_in[0];
    const float* wq = (const float*)d_in[1];
    const float* wk = (const float*)d_in[2];
    const float* wv = (const float*)d_in[3];
    const float* wo = (const float*)d_in[4];
    float* out = (float*)d_out;

    __nv_bfloat16 *xh, *xl, *qh, *ql, *kh, *kl, *vh, *vl, *ch, *cl;
    __nv_bfloat16 *wqh, *wql, *wkh, *wkl, *wvh, *wvl, *woh, *wol;
    cudaGetSymbolAddress((void**)&xh, g_xh);   cudaGetSymbolAddress((void**)&xl, g_xl);
    cudaGetSymbolAddress((void**)&qh, g_qh);   cudaGetSymbolAddress((void**)&ql, g_ql);
    cudaGetSymbolAddress((void**)&kh, g_kh);   cudaGetSymbolAddress((void**)&kl, g_kl);
    cudaGetSymbolAddress((void**)&vh, g_vh);   cudaGetSymbolAddress((void**)&vl, g_vl);
    cudaGetSymbolAddress((void**)&ch, g_ch);   cudaGetSymbolAddress((void**)&cl, g_cl);
    cudaGetSymbolAddress((void**)&wqh, g_wqh); cudaGetSymbolAddress((void**)&wql, g_wql);
    cudaGetSymbolAddress((void**)&wkh, g_wkh); cudaGetSymbolAddress((void**)&wkl, g_wkl);
    cudaGetSymbolAddress((void**)&wvh, g_wvh); cudaGetSymbolAddress((void**)&wvl, g_wvl);
    cudaGetSymbolAddress((void**)&woh, g_woh); cudaGetSymbolAddress((void**)&wol, g_wol);

    cudaFuncSetAttribute(mm_mma_kernel, cudaFuncAttributeMaxDynamicSharedMemorySize, MM_SMEM);
    cudaFuncSetAttribute(flash_mma_kernel, cudaFuncAttributeMaxDynamicSharedMemorySize, FLASH_SMEM);

    // 1) RoPE tables + splits
    rope_table_kernel<<<(SEQ * HALF_D) / 1024, 1024>>>();
    split_kernel<<<(MROWS * DMODEL) / 1024, 256>>>(x, xh, xl);
    split_kernel<<<(DMODEL * DMODEL) / 1024, 256>>>(wq, wqh, wql);
    split_kernel<<<(DMODEL * DMODEL) / 1024, 256>>>(wk, wkh, wkl);
    split_kernel<<<(DMODEL * DMODEL) / 1024, 256>>>(wv, wvh, wvl);
    split_kernel<<<(DMODEL * DMODEL) / 1024, 256>>>(wo, woh, wol);

    // 2) projections -> bf16 hi/lo (RoPE fused; Q pre-scaled by 1/sqrt(d))
    dim3 gg(MROWS / 128, DMODEL / 128);
    mm_mma_kernel<<<gg, 256, MM_SMEM>>>(xh, xl, wqh, wql, nullptr, qh, ql, 1, SCALE);
    mm_mma_kernel<<<gg, 256, MM_SMEM>>>(xh, xl, wkh, wkl, nullptr, kh, kl, 1, 1.0f);
    mm_mma_kernel<<<gg, 256, MM_SMEM>>>(xh, xl, wvh, wvl, nullptr, vh, vl, 0, 1.0f);

    // 3) tensor-core flash attention -> ctx bf16 hi/lo
    flash_mma_kernel<<<dim3(SEQ / 128, NHEAD, BATCH), 256, FLASH_SMEM>>>(
        qh, ql, kh, kl, vh, vl, ch, cl);

    // 4) output projection -> fp32 out
    mm_mma_kernel<<<gg, 256, MM_SMEM>>>(ch, cl, woh, wol, out, nullptr, nullptr, 0, 1.0f);
}